// round 4
// baseline (speedup 1.0000x reference)
#include <cuda_runtime.h>
#include <math.h>

#define Bv 128
#define Tv 64
#define Cv 66
#define Sv 512
#define Wwin 32
#define G3 1536
#define TENC 63
#define NSTEP 127
#define BG3 (Bv * G3)

// ---------------- device scratch ----------------
__device__ float g_h0[Bv * Sv];
__device__ float g_h1[Bv * Sv];
__device__ float g_hist[NSTEP * Bv * Sv];
__device__ float g_gi0[TENC * BG3];   // precomputed encoder x@Wih0^T (NO bias)
__device__ float g_gi0d[BG3];         // decoder frame@Wih0^T (NO bias)
__device__ float g_p_gh0[4][BG3];     // split-K4 partials
__device__ float g_p_gh1[4][BG3];
__device__ float g_p_gi1[4][BG3];
__device__ float g_frame[Bv * Cv];
__device__ unsigned int g_arrive;

// ---------------- packed fp32x2 helpers ----------------
__device__ __forceinline__ unsigned long long pack2(float a, float b) {
    unsigned long long r;
    asm("mov.b64 %0, {%1, %2};" : "=l"(r) : "f"(a), "f"(b));
    return r;
}
__device__ __forceinline__ unsigned long long ffma2(
    unsigned long long a, unsigned long long b, unsigned long long c) {
    unsigned long long d;
    asm("fma.rn.f32x2 %0, %1, %2, %3;" : "=l"(d) : "l"(a), "l"(b), "l"(c));
    return d;
}
union F2U { unsigned long long u; float2 f; };

// ---------------- grid barrier (nblk = total resident blocks) ----------------
__device__ __forceinline__ void gsync(unsigned int &tgt, int nblk) {
    __syncthreads();
    tgt += (unsigned)nblk;
    if (threadIdx.x == 0) {
        __threadfence();
        atomicAdd(&g_arrive, 1u);
        while (*(volatile unsigned int *)&g_arrive < tgt) { }
        __threadfence();
    }
    __syncthreads();
}

__device__ __forceinline__ float sigf(float v) { return 1.f / (1.f + expf(-v)); }

__device__ __forceinline__ float4 ldcg4(const float *p) {
    return __ldcg(reinterpret_cast<const float4 *>(p));
}
__device__ __forceinline__ float4 ldg4(const float *p) {
    return __ldg(reinterpret_cast<const float4 *>(p));
}
__device__ __forceinline__ float4 add4(float4 a, float4 b) {
    return make_float4(a.x + b.x, a.y + b.y, a.z + b.z, a.w + b.w);
}

// ---------------- 64x64 tile GEMM over K window [k0, k0+kLen), raw partial out
__device__ __forceinline__ void gemm_tile(
    const float *__restrict__ A, int lda,
    const float *__restrict__ Wm, int ldw,
    float *__restrict__ Out,
    int m0, int n0, int k0, int kLen,
    float *shA, float *shW)
{
    const int tid = threadIdx.x;
    const int tx = tid & 15;
    const int ty = tid >> 4;
    const int lr = tid >> 5;   // 0..7
    const int lc = tid & 31;   // k lane within chunk
    unsigned long long acc2[4][2];
#pragma unroll
    for (int i = 0; i < 4; i++) { acc2[i][0] = 0ull; acc2[i][1] = 0ull; }

    const int nCh = (kLen + 31) >> 5;
    float pa[8], pw[8];
    {
        const bool ok = lc < kLen;
#pragma unroll
        for (int it = 0; it < 8; it++) {
            int r = lr + it * 8;
            pa[it] = ok ? __ldcg(&A[(m0 + r) * lda + k0 + lc]) : 0.f;
            pw[it] = ok ? __ldg(&Wm[(n0 + r) * ldw + k0 + lc]) : 0.f;
        }
    }

    for (int ch = 0; ch < nCh; ++ch) {
        __syncthreads();
#pragma unroll
        for (int it = 0; it < 8; it++) {
            int r = lr + it * 8;
            shA[lc * 68 + r] = pa[it];
            shW[lc * 68 + r] = pw[it];
        }
        if (ch + 1 < nCh) {
            int kk = ((ch + 1) << 5) + lc;
            const bool ok = kk < kLen;
#pragma unroll
            for (int it = 0; it < 8; it++) {
                int r = lr + it * 8;
                pa[it] = ok ? __ldcg(&A[(m0 + r) * lda + k0 + kk]) : 0.f;
                pw[it] = ok ? __ldg(&Wm[(n0 + r) * ldw + k0 + kk]) : 0.f;
            }
        }
        __syncthreads();
#pragma unroll
        for (int k = 0; k < 32; ++k) {
            const float4 avv = *reinterpret_cast<const float4 *>(shA + k * 68 + (ty << 2));
            const ulonglong2 bp = *reinterpret_cast<const ulonglong2 *>(shW + k * 68 + (tx << 2));
            const unsigned long long a0 = pack2(avv.x, avv.x);
            const unsigned long long a1 = pack2(avv.y, avv.y);
            const unsigned long long a2 = pack2(avv.z, avv.z);
            const unsigned long long a3 = pack2(avv.w, avv.w);
            acc2[0][0] = ffma2(a0, bp.x, acc2[0][0]);
            acc2[0][1] = ffma2(a0, bp.y, acc2[0][1]);
            acc2[1][0] = ffma2(a1, bp.x, acc2[1][0]);
            acc2[1][1] = ffma2(a1, bp.y, acc2[1][1]);
            acc2[2][0] = ffma2(a2, bp.x, acc2[2][0]);
            acc2[2][1] = ffma2(a2, bp.y, acc2[2][1]);
            acc2[3][0] = ffma2(a3, bp.x, acc2[3][0]);
            acc2[3][1] = ffma2(a3, bp.y, acc2[3][1]);
        }
    }
#pragma unroll
    for (int i = 0; i < 4; i++) {
        F2U u0, u1;
        u0.u = acc2[i][0];
        u1.u = acc2[i][1];
        float4 v = make_float4(u0.f.x, u0.f.y, u1.f.x, u1.f.y);
        *reinterpret_cast<float4 *>(&Out[(m0 + (ty << 2) + i) * G3 + n0 + (tx << 2)]) = v;
    }
}

// ---------------- kernel 1: init + precompute encoder gi0 (no bias) --------
__global__ void __launch_bounds__(256) pre_kernel(
    const float *__restrict__ x,
    const float *__restrict__ Wih0)
{
    __shared__ __align__(16) float shA[32 * 68];
    __shared__ __align__(16) float shW[32 * 68];
    const int tid = threadIdx.x;

    if (blockIdx.x == 0) {
        for (int i = tid; i < Bv * Sv; i += 256) { g_h0[i] = 0.f; g_h1[i] = 0.f; }
        for (int i = tid; i < Bv * Cv; i += 256) {
            int b = i / Cv, c = i - b * Cv;
            g_frame[i] = x[b * Tv * Cv + (Tv - 1) * Cv + c];
        }
        if (tid == 0) g_arrive = 0u;
    }

    const int rt = blockIdx.x / 24;
    const int nt = blockIdx.x % 24;
    const int r0 = rt * 64, n0 = nt * 64;
    const int tx = tid & 15, ty = tid >> 4;
    const int lr = tid >> 5, lc = tid & 31;

    unsigned long long acc2[4][2];
#pragma unroll
    for (int i = 0; i < 4; i++) { acc2[i][0] = 0ull; acc2[i][1] = 0ull; }

    for (int kc = 0; kc < Cv; kc += 32) {
        __syncthreads();
#pragma unroll
        for (int it = 0; it < 8; it++) {
            int r = lr + it * 8;
            int kk = kc + lc;
            float av = 0.f, wv = 0.f;
            if (kk < Cv) {
                int rr = r0 + r;
                int t = rr >> 7, b = rr & 127;
                av = __ldg(&x[b * (Tv * Cv) + t * Cv + kk]);
                wv = __ldg(&Wih0[(n0 + r) * Cv + kk]);
            }
            shA[lc * 68 + r] = av;
            shW[lc * 68 + r] = wv;
        }
        __syncthreads();
#pragma unroll
        for (int k = 0; k < 32; ++k) {
            const float4 avv = *reinterpret_cast<const float4 *>(shA + k * 68 + (ty << 2));
            const ulonglong2 bp = *reinterpret_cast<const ulonglong2 *>(shW + k * 68 + (tx << 2));
            const unsigned long long a0 = pack2(avv.x, avv.x);
            const unsigned long long a1 = pack2(avv.y, avv.y);
            const unsigned long long a2 = pack2(avv.z, avv.z);
            const unsigned long long a3 = pack2(avv.w, avv.w);
            acc2[0][0] = ffma2(a0, bp.x, acc2[0][0]);
            acc2[0][1] = ffma2(a0, bp.y, acc2[0][1]);
            acc2[1][0] = ffma2(a1, bp.x, acc2[1][0]);
            acc2[1][1] = ffma2(a1, bp.y, acc2[1][1]);
            acc2[2][0] = ffma2(a2, bp.x, acc2[2][0]);
            acc2[2][1] = ffma2(a2, bp.y, acc2[2][1]);
            acc2[3][0] = ffma2(a3, bp.x, acc2[3][0]);
            acc2[3][1] = ffma2(a3, bp.y, acc2[3][1]);
        }
    }
#pragma unroll
    for (int i = 0; i < 4; i++) {
        int rr = r0 + (ty << 2) + i;
        int t = rr >> 7, b = rr & 127;
        F2U u0, u1;
        u0.u = acc2[i][0];
        u1.u = acc2[i][1];
        float4 v = make_float4(u0.f.x, u0.f.y, u1.f.x, u1.f.y);
        *reinterpret_cast<float4 *>(&g_gi0[t * BG3 + b * G3 + n0 + (tx << 2)]) = v;
    }
}

// ---------------- kernel 2: persistent sequential RNN (2 blocks / SM) -------
__global__ void __launch_bounds__(256, 2) rnn_kernel(
    const float *__restrict__ Wih0, const float *__restrict__ bih0,
    const float *__restrict__ Whh0, const float *__restrict__ bhh0,
    const float *__restrict__ Wih1, const float *__restrict__ bih1,
    const float *__restrict__ Whh1, const float *__restrict__ bhh1,
    const float *__restrict__ Wt, const float *__restrict__ bt,
    const float *__restrict__ Ws, const float *__restrict__ bs,
    float *__restrict__ out, int nblk)
{
    __shared__ __align__(16) float shA[32 * 68];
    __shared__ __align__(16) float shW[32 * 68];
    __shared__ float shWt[32];
    const int bid = blockIdx.x;
    const int tid = threadIdx.x;
    const int nth = nblk * 256;
    const int gtid = bid * 256 + tid;
    unsigned int tgt = 0;

    for (int step = 0; step < NSTEP; step++) {
        const bool dec = (step >= TENC);
        const int d = step - TENC;

        // ======== Phase A: gh0 (K4: 192) + gh1 kq0,1 (96) + [dec] gi0d (48)
        {
            const int ntA = dec ? 336 : 288;
            for (int task = bid; task < ntA; task += nblk) {
                if (task < 192) {
                    int kq = task / 48, sub = task % 48;
                    int m0 = (sub / 24) * 64, n0 = (sub % 24) * 64;
                    gemm_tile(g_h0, Sv, Whh0, Sv, g_p_gh0[kq],
                              m0, n0, kq * 128, 128, shA, shW);
                } else if (task < 288) {
                    int t2 = task - 192;
                    int kq = t2 / 48, sub = t2 % 48;
                    int m0 = (sub / 24) * 64, n0 = (sub % 24) * 64;
                    gemm_tile(g_h1, Sv, Whh1, Sv, g_p_gh1[kq],
                              m0, n0, kq * 128, 128, shA, shW);
                } else {
                    int sub = task - 288;
                    int m0 = (sub / 24) * 64, n0 = (sub % 24) * 64;
                    gemm_tile(g_frame, Cv, Wih0, Cv, g_gi0d,
                              m0, n0, 0, Cv, shA, shW);
                }
            }
        }
        gsync(tgt, nblk);

        // ======== gate0: h0 update
        {
            const float *GI = dec ? g_gi0d : (g_gi0 + step * BG3);
            for (int g = gtid; g < (Bv * Sv) / 4; g += nth) {
                int v = g << 2;
                int b = v >> 9, s = v & 511;
                const int rb = b * G3 + s;

                float4 ir = add4(ldcg4(GI + rb), ldg4(bih0 + s));
                float4 iz = add4(ldcg4(GI + rb + 512), ldg4(bih0 + 512 + s));
                float4 in_ = add4(ldcg4(GI + rb + 1024), ldg4(bih0 + 1024 + s));
                float4 hr = ldg4(bhh0 + s);
                float4 hz = ldg4(bhh0 + 512 + s);
                float4 hn = ldg4(bhh0 + 1024 + s);
#pragma unroll
                for (int kq = 0; kq < 4; kq++) {
                    hr = add4(hr, ldcg4(g_p_gh0[kq] + rb));
                    hz = add4(hz, ldcg4(g_p_gh0[kq] + rb + 512));
                    hn = add4(hn, ldcg4(g_p_gh0[kq] + rb + 1024));
                }
                float4 hold = ldcg4(g_h0 + v);

                float res[4];
                float irv[4] = {ir.x, ir.y, ir.z, ir.w};
                float izv[4] = {iz.x, iz.y, iz.z, iz.w};
                float inv[4] = {in_.x, in_.y, in_.z, in_.w};
                float hrv[4] = {hr.x, hr.y, hr.z, hr.w};
                float hzv[4] = {hz.x, hz.y, hz.z, hz.w};
                float hnv[4] = {hn.x, hn.y, hn.z, hn.w};
                float hov[4] = {hold.x, hold.y, hold.z, hold.w};
#pragma unroll
                for (int q = 0; q < 4; q++) {
                    float r = sigf(irv[q] + hrv[q]);
                    float z = sigf(izv[q] + hzv[q]);
                    float n = tanhf(inv[q] + r * hnv[q]);
                    res[q] = (1.f - z) * n + z * hov[q];
                }
                *reinterpret_cast<float4 *>(g_h0 + v) =
                    make_float4(res[0], res[1], res[2], res[3]);
            }
        }
        gsync(tgt, nblk);

        // ======== Phase B: gi1 (K4: 192) + gh1 kq2,3 (96)
        {
            for (int task = bid; task < 288; task += nblk) {
                if (task < 192) {
                    int kq = task / 48, sub = task % 48;
                    int m0 = (sub / 24) * 64, n0 = (sub % 24) * 64;
                    gemm_tile(g_h0, Sv, Wih1, Sv, g_p_gi1[kq],
                              m0, n0, kq * 128, 128, shA, shW);
                } else {
                    int t2 = task - 192;
                    int kq = 2 + t2 / 48, sub = t2 % 48;
                    int m0 = (sub / 24) * 64, n0 = (sub % 24) * 64;
                    gemm_tile(g_h1, Sv, Whh1, Sv, g_p_gh1[kq],
                              m0, n0, kq * 128, 128, shA, shW);
                }
            }
        }
        gsync(tgt, nblk);

        // ======== gate1 (+ hist, window) + decoder projection, block b = row b
        if (bid < Bv) {
            const int b = bid;
            float *shT = shA;            // 512 floats (temp)
            float *shR = shW;            // partial dot results
            if (dec && tid < 32) shWt[tid] = __ldg(&Wt[tid]);
            __syncthreads();
            const float bt0 = __ldg(&bt[0]);

            for (int s = tid; s < Sv; s += 256) {
                const int rb = b * G3 + s;
                float ir = __ldg(&bih1[s]);
                float iz = __ldg(&bih1[512 + s]);
                float in_ = __ldg(&bih1[1024 + s]);
                float hr = __ldg(&bhh1[s]);
                float hz = __ldg(&bhh1[512 + s]);
                float hn = __ldg(&bhh1[1024 + s]);
#pragma unroll
                for (int kq = 0; kq < 4; kq++) {
                    ir += __ldcg(g_p_gi1[kq] + rb);
                    iz += __ldcg(g_p_gi1[kq] + rb + 512);
                    in_ += __ldcg(g_p_gi1[kq] + rb + 1024);
                    hr += __ldcg(g_p_gh1[kq] + rb);
                    hz += __ldcg(g_p_gh1[kq] + rb + 512);
                    hn += __ldcg(g_p_gh1[kq] + rb + 1024);
                }
                float r = sigf(ir + hr);
                float z = sigf(iz + hz);
                float n = tanhf(in_ + r * hn);
                float h1n = (1.f - z) * n + z * g_h1[b * Sv + s];
                g_h1[b * Sv + s] = h1n;
                g_hist[step * (Bv * Sv) + b * Sv + s] = h1n;
                if (dec) {
                    float acc = bt0;
                    const float *hp = g_hist + b * Sv + s;
#pragma unroll
                    for (int w = 0; w < Wwin - 1; w++)
                        acc += shWt[w] * hp[(32 + d + w) * (Bv * Sv)];
                    acc += shWt[Wwin - 1] * h1n;
                    shT[s] = acc;
                }
            }
            if (dec) {
                __syncthreads();
                if (tid < 2 * Cv) {
                    int c = tid >> 1, h = tid & 1;
                    const float *wr = Ws + c * Sv + h * 256;
                    const float *tr = shT + h * 256;
                    float p0 = 0.f, p1 = 0.f, p2 = 0.f, p3 = 0.f;
#pragma unroll 4
                    for (int s = 0; s < 256; s += 4) {
                        p0 += tr[s + 0] * __ldg(&wr[s + 0]);
                        p1 += tr[s + 1] * __ldg(&wr[s + 1]);
                        p2 += tr[s + 2] * __ldg(&wr[s + 2]);
                        p3 += tr[s + 3] * __ldg(&wr[s + 3]);
                    }
                    shR[tid] = (p0 + p1) + (p2 + p3);
                }
                __syncthreads();
                if (tid < Cv) {
                    float ov = shR[2 * tid] + shR[2 * tid + 1] + __ldg(&bs[tid]);
                    float nf = ov + g_frame[b * Cv + tid];
                    out[b * (Tv * Cv) + d * Cv + tid] = nf;
                    g_frame[b * Cv + tid] = nf;
                }
            }
        }
        gsync(tgt, nblk);
    }
}

// ---------------- launch ----------------
extern "C" void kernel_launch(void *const *d_in, const int *in_sizes, int n_in,
                              void *d_out, int out_size)
{
    const float *x    = (const float *)d_in[0];
    const float *Wih0 = (const float *)d_in[1];
    const float *Whh0 = (const float *)d_in[2];
    const float *bih0 = (const float *)d_in[3];
    const float *bhh0 = (const float *)d_in[4];
    const float *Wih1 = (const float *)d_in[5];
    const float *Whh1 = (const float *)d_in[6];
    const float *bih1 = (const float *)d_in[7];
    const float *bhh1 = (const float *)d_in[8];
    const float *Wt   = (const float *)d_in[9];
    const float *bt   = (const float *)d_in[10];
    const float *Ws   = (const float *)d_in[11];
    const float *bs   = (const float *)d_in[12];
    float *out = (float *)d_out;

    int dev = 0;
    cudaGetDevice(&dev);
    int nsm = 0;
    cudaDeviceGetAttribute(&nsm, cudaDevAttrMultiProcessorCount, dev);
    if (nsm <= 0) nsm = 148;
    const int nblk = 2 * nsm;

    pre_kernel<<<126 * 24, 256>>>(x, Wih0);
    rnn_kernel<<<nblk, 256>>>(Wih0, bih0, Whh0, bhh0, Wih1, bih1, Whh1, bhh1,
                              Wt, bt, Ws, bs, out, nblk);
}

// round 6
// speedup vs baseline: 1.8353x; 1.8353x over previous
#include <cuda_runtime.h>
#include <cuda_bf16.h>
#include <math.h>

#define Bv 128
#define Tv 64
#define Cv 66
#define Sv 512
#define Wwin 32
#define G3 1536
#define TENC 63
#define NSTEP 127
#define BG3 (Bv * G3)
#define KC 64
#define BUFSZ 32768
#define SMEM_DYN (2 * BUFSZ + 2048)

// ---------------- device scratch ----------------
__device__ float g_h0[Bv * Sv];
__device__ float g_h1[Bv * Sv];
__device__ float g_hist[NSTEP * Bv * Sv];
__device__ float g_gi0[TENC * BG3];
__device__ float g_gi0d[BG3];
__device__ float g_p_gh0[2][BG3];
__device__ float g_p_gh1[2][BG3];
__device__ float g_p_gi1[2][BG3];
__device__ float g_frame[Bv * Cv];
__device__ unsigned int g_arrive;

__device__ __nv_bfloat16 g_h0hi[Bv * Sv], g_h0lo[Bv * Sv];
__device__ __nv_bfloat16 g_h1hi[Bv * Sv], g_h1lo[Bv * Sv];
__device__ __nv_bfloat16 g_fhi[Bv * 128], g_flo[Bv * 128];     // frame, K padded to 128
__device__ __nv_bfloat16 g_whh0hi[G3 * Sv], g_whh0lo[G3 * Sv];
__device__ __nv_bfloat16 g_whh1hi[G3 * Sv], g_whh1lo[G3 * Sv];
__device__ __nv_bfloat16 g_wih1hi[G3 * Sv], g_wih1lo[G3 * Sv];
__device__ __nv_bfloat16 g_w0hi[G3 * 128], g_w0lo[G3 * 128];   // Wih0, K padded to 128

// ---------------- helpers ----------------
__device__ __forceinline__ unsigned smem_u32(const void *p) {
    unsigned a;
    asm("{ .reg .u64 t; cvta.to.shared.u64 t, %1; cvt.u32.u64 %0, t; }" : "=r"(a) : "l"(p));
    return a;
}
__device__ __forceinline__ void cpa16(unsigned dst, const void *src) {
    asm volatile("cp.async.cg.shared.global [%0], [%1], 16;" :: "r"(dst), "l"(src));
}
__device__ __forceinline__ void cpa_commit() {
    asm volatile("cp.async.commit_group;" ::: "memory");
}
template <int N> __device__ __forceinline__ void cpa_wait() {
    asm volatile("cp.async.wait_group %0;" :: "n"(N) : "memory");
}
#define LDSM4(R, addr) \
    asm volatile("ldmatrix.sync.aligned.m8n8.x4.shared.b16 {%0,%1,%2,%3}, [%4];" \
        : "=r"((R)[0]), "=r"((R)[1]), "=r"((R)[2]), "=r"((R)[3]) : "r"(addr))
#define MMA(D, A, b0, b1) \
    asm volatile("mma.sync.aligned.m16n8k16.row.col.f32.bf16.bf16.f32 " \
        "{%0,%1,%2,%3}, {%4,%5,%6,%7}, {%8,%9}, {%0,%1,%2,%3};" \
        : "+f"((D)[0]), "+f"((D)[1]), "+f"((D)[2]), "+f"((D)[3]) \
        : "r"((A)[0]), "r"((A)[1]), "r"((A)[2]), "r"((A)[3]), "r"(b0), "r"(b1))

__device__ __forceinline__ float sigf(float v) { return 1.f / (1.f + expf(-v)); }
__device__ __forceinline__ float4 ldcg4(const float *p) { return __ldcg((const float4 *)p); }
__device__ __forceinline__ float4 ldg4(const float *p) { return __ldg((const float4 *)p); }
__device__ __forceinline__ float4 add4(float4 a, float4 b) {
    return make_float4(a.x + b.x, a.y + b.y, a.z + b.z, a.w + b.w);
}
__device__ __forceinline__ void split_bf16(float v, __nv_bfloat16 &hi, __nv_bfloat16 &lo) {
    hi = __float2bfloat16(v);
    lo = __float2bfloat16(v - __bfloat162float(hi));
}

// ---------------- grid barrier ----------------
__device__ __forceinline__ void gsync(unsigned &tgt, int nblk) {
    __syncthreads();
    tgt += (unsigned)nblk;
    if (threadIdx.x == 0) {
        __threadfence();
        atomicAdd(&g_arrive, 1u);
        while (*(volatile unsigned *)&g_arrive < tgt) { }
        __threadfence();
    }
    __syncthreads();
}

// ---------------- stage one 64x64 bf16 chunk x4 arrays via cp.async ----------
// swizzled rows of 128B: byte = r*128 + ((c16 ^ (r&7)) << 4)
__device__ __forceinline__ void stage_chunk(unsigned buf,
    const __nv_bfloat16 *__restrict__ Ahi, const __nv_bfloat16 *__restrict__ Alo, int lda,
    const __nv_bfloat16 *__restrict__ Whi, const __nv_bfloat16 *__restrict__ Wlo, int ldw)
{
    const int t = threadIdx.x;
#pragma unroll
    for (int it = 0; it < 2; it++) {
        int idx = t + it * 256;
        int r = idx >> 3, c = idx & 7;
        unsigned off = (unsigned)(r * 128) + (unsigned)((c ^ (r & 7)) << 4);
        const int so = r * lda + c * 8;
        const int sw = r * ldw + c * 8;
        cpa16(buf + off, Ahi + so);
        cpa16(buf + 8192 + off, Alo + so);
        cpa16(buf + 16384 + off, Whi + sw);
        cpa16(buf + 24576 + off, Wlo + sw);
    }
}

// ---------------- HMMA on one staged 64x64 chunk --------------------------
__device__ __forceinline__ void hmma_chunk(unsigned buf, int wm, int wn, int lane,
                                           float acc[2][2][4])
{
    const int lr = lane & 15;
    const int lh = lane >> 4;
#pragma unroll
    for (int ks = 0; ks < 4; ks++) {
        unsigned ah[2][4], al[2][4], bh[4], bl[4];
#pragma unroll
        for (int mt = 0; mt < 2; mt++) {
            int r = wm * 32 + mt * 16 + lr;
            unsigned ad = buf + r * 128 + ((unsigned)((ks * 2 + lh) ^ (r & 7)) << 4);
            LDSM4(ah[mt], ad);
            LDSM4(al[mt], ad + 8192);
        }
        {
            int r = wn * 16 + lr;
            unsigned bd = buf + 16384 + r * 128 + ((unsigned)((ks * 2 + lh) ^ (r & 7)) << 4);
            LDSM4(bh, bd);
            LDSM4(bl, bd + 8192);
        }
#pragma unroll
        for (int mt = 0; mt < 2; mt++) {
#pragma unroll
            for (int nt = 0; nt < 2; nt++) {
                unsigned h0 = nt ? bh[1] : bh[0], h1 = nt ? bh[3] : bh[2];
                unsigned l0 = nt ? bl[1] : bl[0], l1 = nt ? bl[3] : bl[2];
                MMA(acc[mt][nt], ah[mt], h0, h1);   // hi*hi
                MMA(acc[mt][nt], ah[mt], l0, l1);   // hi*lo
                MMA(acc[mt][nt], al[mt], h0, h1);   // lo*hi
            }
        }
    }
}

// ---------------- full 64x64 tile task (double-buffered chunks) -----------
__device__ void hmma_tile(
    const __nv_bfloat16 *__restrict__ Ahi, const __nv_bfloat16 *__restrict__ Alo, int lda,
    const __nv_bfloat16 *__restrict__ Whi, const __nv_bfloat16 *__restrict__ Wlo, int ldw,
    float *__restrict__ Out, int m0, int n0, int k0, int nCh, char *dyn)
{
    const int tid = threadIdx.x;
    const int lane = tid & 31;
    const int w = tid >> 5;
    const int wm = w & 1, wn = w >> 1;
    const unsigned sb = smem_u32(dyn);

    float acc[2][2][4];
#pragma unroll
    for (int a = 0; a < 2; a++)
#pragma unroll
        for (int b = 0; b < 2; b++)
#pragma unroll
            for (int c = 0; c < 4; c++) acc[a][b][c] = 0.f;

    const __nv_bfloat16 *a0 = Ahi + m0 * lda + k0;
    const __nv_bfloat16 *a1 = Alo + m0 * lda + k0;
    const __nv_bfloat16 *w0 = Whi + n0 * ldw + k0;
    const __nv_bfloat16 *w1 = Wlo + n0 * ldw + k0;

    stage_chunk(sb, a0, a1, lda, w0, w1, ldw);
    cpa_commit();
    for (int ch = 0; ch < nCh; ch++) {
        if (ch + 1 < nCh) {
            int kc = (ch + 1) * KC;
            stage_chunk(sb + (unsigned)(((ch + 1) & 1) * BUFSZ),
                        a0 + kc, a1 + kc, lda, w0 + kc, w1 + kc, ldw);
            cpa_commit();
            cpa_wait<1>();
        } else {
            cpa_wait<0>();
        }
        __syncthreads();
        hmma_chunk(sb + (unsigned)((ch & 1) * BUFSZ), wm, wn, lane, acc);
        __syncthreads();
    }

    const int r0 = m0 + wm * 32 + (lane >> 2);
    const int cb = n0 + wn * 16 + (lane & 3) * 2;
#pragma unroll
    for (int mt = 0; mt < 2; mt++)
#pragma unroll
        for (int nt = 0; nt < 2; nt++) {
            float *p = Out + (r0 + mt * 16) * G3 + cb + nt * 8;
            *(float2 *)p = make_float2(acc[mt][nt][0], acc[mt][nt][1]);
            *(float2 *)(p + 8 * G3) = make_float2(acc[mt][nt][2], acc[mt][nt][3]);
        }
}

// ---------------- packed fp32x2 (pre_kernel GEMM) ----------------
__device__ __forceinline__ unsigned long long pack2(float a, float b) {
    unsigned long long r;
    asm("mov.b64 %0, {%1, %2};" : "=l"(r) : "f"(a), "f"(b));
    return r;
}
__device__ __forceinline__ unsigned long long ffma2(
    unsigned long long a, unsigned long long b, unsigned long long c) {
    unsigned long long d;
    asm("fma.rn.f32x2 %0, %1, %2, %3;" : "=l"(d) : "l"(a), "l"(b), "l"(c));
    return d;
}
union F2U { unsigned long long u; float2 f; };

// ---------------- kernel 1: init + encoder gi0 + weight conversions --------
__global__ void __launch_bounds__(256) pre_kernel(
    const float *__restrict__ x,
    const float *__restrict__ Wih0,
    const float *__restrict__ Whh0,
    const float *__restrict__ Whh1,
    const float *__restrict__ Wih1)
{
    __shared__ __align__(16) float shA[32 * 68];
    __shared__ __align__(16) float shW[32 * 68];
    const int tid = threadIdx.x;
    const int bx = blockIdx.x;

    if (bx < 64) {
        for (int i = bx * 256 + tid; i < Bv * Sv; i += 64 * 256) {
            g_h0[i] = 0.f; g_h1[i] = 0.f;
            __nv_bfloat16 z = __float2bfloat16(0.f);
            g_h0hi[i] = z; g_h0lo[i] = z; g_h1hi[i] = z; g_h1lo[i] = z;
        }
    }
    if (bx == 64) {
        for (int i = tid; i < Bv * 128; i += 256) {
            int b = i >> 7, c = i & 127;
            float v = (c < Cv) ? x[b * Tv * Cv + (Tv - 1) * Cv + c] : 0.f;
            __nv_bfloat16 hi, lo;
            split_bf16(v, hi, lo);
            g_fhi[i] = hi; g_flo[i] = lo;
            if (c < Cv) g_frame[b * Cv + c] = v;
        }
        if (tid == 0) g_arrive = 0u;
    }
    {
        const int NW = G3 * Sv;
        const int TOT = 3 * NW + G3 * 128;
        const int stride = gridDim.x * 256;
        for (int i = bx * 256 + tid; i < TOT; i += stride) {
            __nv_bfloat16 hi, lo;
            if (i < NW) {
                split_bf16(__ldg(&Whh0[i]), hi, lo);
                g_whh0hi[i] = hi; g_whh0lo[i] = lo;
            } else if (i < 2 * NW) {
                int j = i - NW;
                split_bf16(__ldg(&Whh1[j]), hi, lo);
                g_whh1hi[j] = hi; g_whh1lo[j] = lo;
            } else if (i < 3 * NW) {
                int j = i - 2 * NW;
                split_bf16(__ldg(&Wih1[j]), hi, lo);
                g_wih1hi[j] = hi; g_wih1lo[j] = lo;
            } else {
                int j = i - 3 * NW;
                int n = j >> 7, k = j & 127;
                float v = (k < Cv) ? __ldg(&Wih0[n * Cv + k]) : 0.f;
                split_bf16(v, hi, lo);
                g_w0hi[j] = hi; g_w0lo[j] = lo;
            }
        }
    }

    // encoder gi0 tile (fp32, full precision — off critical path)
    const int rt = bx / 24;
    const int nt = bx % 24;
    const int r0 = rt * 64, n0 = nt * 64;
    const int tx = tid & 15, ty = tid >> 4;
    const int lr = tid >> 5, lc = tid & 31;

    unsigned long long acc2[4][2];
#pragma unroll
    for (int i = 0; i < 4; i++) { acc2[i][0] = 0ull; acc2[i][1] = 0ull; }

    for (int kc = 0; kc < Cv; kc += 32) {
        __syncthreads();
#pragma unroll
        for (int it = 0; it < 8; it++) {
            int r = lr + it * 8;
            int kk = kc + lc;
            float av = 0.f, wv = 0.f;
            if (kk < Cv) {
                int rr = r0 + r;
                int t = rr >> 7, b = rr & 127;
                av = __ldg(&x[b * (Tv * Cv) + t * Cv + kk]);
                wv = __ldg(&Wih0[(n0 + r) * Cv + kk]);
            }
            shA[lc * 68 + r] = av;
            shW[lc * 68 + r] = wv;
        }
        __syncthreads();
#pragma unroll
        for (int k = 0; k < 32; ++k) {
            const float4 avv = *(const float4 *)(shA + k * 68 + (ty << 2));
            const ulonglong2 bp = *(const ulonglong2 *)(shW + k * 68 + (tx << 2));
            const unsigned long long q0 = pack2(avv.x, avv.x);
            const unsigned long long q1 = pack2(avv.y, avv.y);
            const unsigned long long q2 = pack2(avv.z, avv.z);
            const unsigned long long q3 = pack2(avv.w, avv.w);
            acc2[0][0] = ffma2(q0, bp.x, acc2[0][0]);
            acc2[0][1] = ffma2(q0, bp.y, acc2[0][1]);
            acc2[1][0] = ffma2(q1, bp.x, acc2[1][0]);
            acc2[1][1] = ffma2(q1, bp.y, acc2[1][1]);
            acc2[2][0] = ffma2(q2, bp.x, acc2[2][0]);
            acc2[2][1] = ffma2(q2, bp.y, acc2[2][1]);
            acc2[3][0] = ffma2(q3, bp.x, acc2[3][0]);
            acc2[3][1] = ffma2(q3, bp.y, acc2[3][1]);
        }
    }
#pragma unroll
    for (int i = 0; i < 4; i++) {
        int rr = r0 + (ty << 2) + i;
        int t = rr >> 7, b = rr & 127;
        F2U u0, u1;
        u0.u = acc2[i][0]; u1.u = acc2[i][1];
        *(float4 *)(&g_gi0[t * BG3 + b * G3 + n0 + (tx << 2)]) =
            make_float4(u0.f.x, u0.f.y, u1.f.x, u1.f.y);
    }
}

// ---------------- kernel 2: persistent RNN with HMMA GEMMs ----------------
__global__ void __launch_bounds__(256, 1) rnn_kernel(
    const float *__restrict__ bih0, const float *__restrict__ bhh0,
    const float *__restrict__ bih1, const float *__restrict__ bhh1,
    const float *__restrict__ Wt, const float *__restrict__ bt,
    const float *__restrict__ Ws, const float *__restrict__ bs,
    float *__restrict__ out, int nblk)
{
    extern __shared__ char dynraw[];
    char *dyn = (char *)(((unsigned long long)dynraw + 1023) & ~1023ull);

    const int bid = blockIdx.x;
    const int tid = threadIdx.x;
    const int nth = nblk * 256;
    const int gtid = bid * 256 + tid;
    unsigned tgt = 0;

    for (int step = 0; step < NSTEP; step++) {
        const bool dec = (step >= TENC);
        const int d = step - TENC;

        // ======== Phase A: gh0 (96) + gh1 kh0 (48) + [dec] gi0d (48)
        {
            const int ntA = dec ? 192 : 144;
            for (int task = bid; task < ntA; task += nblk) {
                if (task < 96) {
                    int kh = task / 48, sub = task % 48;
                    int m0 = (sub / 24) * 64, n0 = (sub % 24) * 64;
                    hmma_tile(g_h0hi, g_h0lo, Sv, g_whh0hi, g_whh0lo, Sv,
                              g_p_gh0[kh], m0, n0, kh * 256, 4, dyn);
                } else if (task < 144) {
                    int sub = task - 96;
                    int m0 = (sub / 24) * 64, n0 = (sub % 24) * 64;
                    hmma_tile(g_h1hi, g_h1lo, Sv, g_whh1hi, g_whh1lo, Sv,
                              g_p_gh1[0], m0, n0, 0, 4, dyn);
                } else {
                    int sub = task - 144;
                    int m0 = (sub / 24) * 64, n0 = (sub % 24) * 64;
                    hmma_tile(g_fhi, g_flo, 128, g_w0hi, g_w0lo, 128,
                              g_gi0d, m0, n0, 0, 2, dyn);
                }
            }
        }
        gsync(tgt, nblk);

        // ======== gate0: h0 update (+ bf16 hi/lo write)
        {
            const float *GI = dec ? g_gi0d : (g_gi0 + step * BG3);
            for (int g = gtid; g < (Bv * Sv) / 4; g += nth) {
                int v = g << 2;
                int b = v >> 9, s = v & 511;
                const int rb = b * G3 + s;

                float4 ir = add4(ldcg4(GI + rb), ldg4(bih0 + s));
                float4 iz = add4(ldcg4(GI + rb + 512), ldg4(bih0 + 512 + s));
                float4 in_ = add4(ldcg4(GI + rb + 1024), ldg4(bih0 + 1024 + s));
                float4 hr = add4(add4(ldcg4(g_p_gh0[0] + rb), ldcg4(g_p_gh0[1] + rb)),
                                 ldg4(bhh0 + s));
                float4 hz = add4(add4(ldcg4(g_p_gh0[0] + rb + 512), ldcg4(g_p_gh0[1] + rb + 512)),
                                 ldg4(bhh0 + 512 + s));
                float4 hn = add4(add4(ldcg4(g_p_gh0[0] + rb + 1024), ldcg4(g_p_gh0[1] + rb + 1024)),
                                 ldg4(bhh0 + 1024 + s));
                float4 hold = ldcg4(g_h0 + v);

                float irv[4] = {ir.x, ir.y, ir.z, ir.w};
                float izv[4] = {iz.x, iz.y, iz.z, iz.w};
                float inv[4] = {in_.x, in_.y, in_.z, in_.w};
                float hrv[4] = {hr.x, hr.y, hr.z, hr.w};
                float hzv[4] = {hz.x, hz.y, hz.z, hz.w};
                float hnv[4] = {hn.x, hn.y, hn.z, hn.w};
                float hov[4] = {hold.x, hold.y, hold.z, hold.w};
                float res[4];
                __nv_bfloat16 rhi[4], rlo[4];
#pragma unroll
                for (int q = 0; q < 4; q++) {
                    float r = sigf(irv[q] + hrv[q]);
                    float z = sigf(izv[q] + hzv[q]);
                    float n = tanhf(inv[q] + r * hnv[q]);
                    res[q] = (1.f - z) * n + z * hov[q];
                    split_bf16(res[q], rhi[q], rlo[q]);
                }
                *(float4 *)(g_h0 + v) = make_float4(res[0], res[1], res[2], res[3]);
                __nv_bfloat162 *ph = (__nv_bfloat162 *)(g_h0hi + v);
                __nv_bfloat162 *pl = (__nv_bfloat162 *)(g_h0lo + v);
                ph[0] = __nv_bfloat162(rhi[0], rhi[1]);
                ph[1] = __nv_bfloat162(rhi[2], rhi[3]);
                pl[0] = __nv_bfloat162(rlo[0], rlo[1]);
                pl[1] = __nv_bfloat162(rlo[2], rlo[3]);
            }
        }
        gsync(tgt, nblk);

        // ======== Phase B: gi1 (96) + gh1 kh1 (48)
        {
            for (int task = bid; task < 144; task += nblk) {
                if (task < 96) {
                    int kh = task / 48, sub = task % 48;
                    int m0 = (sub / 24) * 64, n0 = (sub % 24) * 64;
                    hmma_tile(g_h0hi, g_h0lo, Sv, g_wih1hi, g_wih1lo, Sv,
                              g_p_gi1[kh], m0, n0, kh * 256, 4, dyn);
                } else {
                    int sub = task - 96;
                    int m0 = (sub / 24) * 64, n0 = (sub % 24) * 64;
                    hmma_tile(g_h1hi, g_h1lo, Sv, g_whh1hi, g_whh1lo, Sv,
                              g_p_gh1[1], m0, n0, 256, 4, dyn);
                }
            }
        }
        gsync(tgt, nblk);

        // ======== gate1 (+ hist, window) + decoder projection, block b = row b
        if (bid < Bv) {
            const int b = bid;
            float *shT = (float *)dyn;
            float *shR = shT + 512;
            float *shWt = shR + 160;
            if (dec && tid < 32) shWt[tid] = __ldg(&Wt[tid]);
            __syncthreads();
            const float bt0 = __ldg(&bt[0]);

            for (int s = tid; s < Sv; s += 256) {
                const int rb = b * G3 + s;
                float ir = __ldg(&bih1[s]) + __ldcg(&g_p_gi1[0][rb]) + __ldcg(&g_p_gi1[1][rb]);
                float iz = __ldg(&bih1[512 + s]) + __ldcg(&g_p_gi1[0][rb + 512]) + __ldcg(&g_p_gi1[1][rb + 512]);
                float in_ = __ldg(&bih1[1024 + s]) + __ldcg(&g_p_gi1[0][rb + 1024]) + __ldcg(&g_p_gi1[1][rb + 1024]);
                float hr = __ldg(&bhh1[s]) + __ldcg(&g_p_gh1[0][rb]) + __ldcg(&g_p_gh1[1][rb]);
                float hz = __ldg(&bhh1[512 + s]) + __ldcg(&g_p_gh1[0][rb + 512]) + __ldcg(&g_p_gh1[1][rb + 512]);
                float hn = __ldg(&bhh1[1024 + s]) + __ldcg(&g_p_gh1[0][rb + 1024]) + __ldcg(&g_p_gh1[1][rb + 1024]);
                float r = sigf(ir + hr);
                float z = sigf(iz + hz);
                float n = tanhf(in_ + r * hn);
                float h1n = (1.f - z) * n + z * g_h1[b * Sv + s];
                g_h1[b * Sv + s] = h1n;
                g_hist[step * (Bv * Sv) + b * Sv + s] = h1n;
                __nv_bfloat16 hh, hl;
                split_bf16(h1n, hh, hl);
                g_h1hi[b * Sv + s] = hh;
                g_h1lo[b * Sv + s] = hl;
                if (dec) {
                    float acc = bt0;
                    const float *hp = g_hist + b * Sv + s;
#pragma unroll
                    for (int w = 0; w < Wwin - 1; w++)
                        acc += shWt[w] * hp[(32 + d + w) * (Bv * Sv)];
                    acc += shWt[Wwin - 1] * h1n;
                    shT[s] = acc;
                }
            }
            if (dec) {
                __syncthreads();
                if (tid < 2 * Cv) {
                    int c = tid >> 1, h = tid & 1;
                    const float *wr = Ws + c * Sv + h * 256;
                    const float *tr = shT + h * 256;
                    float p0 = 0.f, p1 = 0.f, p2 = 0.f, p3 = 0.f;
#pragma unroll 4
                    for (int s = 0; s < 256; s += 4) {
                        p0 += tr[s + 0] * __ldg(&wr[s + 0]);
                        p1 += tr[s + 1] * __ldg(&wr[s + 1]);
                        p2 += tr[s + 2] * __ldg(&wr[s + 2]);
                        p3 += tr[s + 3] * __ldg(&wr[s + 3]);
                    }
                    shR[tid] = (p0 + p1) + (p2 + p3);
                }
                __syncthreads();
                if (tid < Cv) {
                    float ov = shR[2 * tid] + shR[2 * tid + 1] + __ldg(&bs[tid]);
                    float nf = ov + g_frame[b * Cv + tid];
                    out[b * (Tv * Cv) + d * Cv + tid] = nf;
                    g_frame[b * Cv + tid] = nf;
                    __nv_bfloat16 fh, fl;
                    split_bf16(nf, fh, fl);
                    g_fhi[b * 128 + tid] = fh;
                    g_flo[b * 128 + tid] = fl;
                }
            }
        }
        gsync(tgt, nblk);
    }
}

// ---------------- launch ----------------
extern "C" void kernel_launch(void *const *d_in, const int *in_sizes, int n_in,
                              void *d_out, int out_size)
{
    const float *x    = (const float *)d_in[0];
    const float *Wih0 = (const float *)d_in[1];
    const float *Whh0 = (const float *)d_in[2];
    const float *bih0 = (const float *)d_in[3];
    const float *bhh0 = (const float *)d_in[4];
    const float *Wih1 = (const float *)d_in[5];
    const float *Whh1 = (const float *)d_in[6];
    const float *bih1 = (const float *)d_in[7];
    const float *bhh1 = (const float *)d_in[8];
    const float *Wt   = (const float *)d_in[9];
    const float *bt   = (const float *)d_in[10];
    const float *Ws   = (const float *)d_in[11];
    const float *bs   = (const float *)d_in[12];
    float *out = (float *)d_out;

    int dev = 0;
    cudaGetDevice(&dev);
    int nsm = 0;
    cudaDeviceGetAttribute(&nsm, cudaDevAttrMultiProcessorCount, dev);
    if (nsm <= 0) nsm = 148;

    cudaFuncSetAttribute(rnn_kernel, cudaFuncAttributeMaxDynamicSharedMemorySize, SMEM_DYN);

    pre_kernel<<<126 * 24, 256>>>(x, Wih0, Whh0, Whh1, Wih1);
    rnn_kernel<<<nsm, 256, SMEM_DYN>>>(bih0, bhh0, bih1, bhh1,
                                       Wt, bt, Ws, bs, out, nsm);
}